// round 3
// baseline (speedup 1.0000x reference)
#include <cuda_runtime.h>

// Shapes fixed by dataset: b=8, n=1024, m=2048, x_dim=1, c=3, Z=128
#define BB    8
#define NN    1024
#define MM    2048
#define ZDIM  128
#define MT    8       // m-rows per block (4 warps x 2 m each)
#define EPSV  1e-8f
#define LOG2E 1.4426950408889634f

__device__ __forceinline__ float ex2f(float v) {
    float r;
    asm("ex2.approx.ftz.f32 %0, %1;" : "=f"(r) : "f"(v));
    return r;
}

__global__ __launch_bounds__(128, 12)
void enc_kernel(const float* __restrict__ x,
                const float* __restrict__ y,
                const float* __restrict__ t,
                const float* __restrict__ sigma,
                const float* __restrict__ W,
                const float* __restrict__ bfc,
                float* __restrict__ out)
{
    __shared__ float4 sx[NN];            // (p = C0*x^2, q = -2*C0*x, y0, y1)  16KB
    __shared__ float4 zfin[MT];          // (density, zn1, zn2, -)
    __shared__ float4 W0s[ZDIM/4], W1s[ZDIM/4], W2s[ZDIM/4], Bs4[ZDIM/4];

    const int tid  = threadIdx.x;
    const int lane = tid & 31;
    const int wrp  = tid >> 5;                  // 0..3, each owns 2 m-rows
    const int blk  = blockIdx.x;
    const int b    = blk >> 8;                  // 256 m-tiles per batch
    const int m_base = (blk & 255) * MT;

    // Per-channel exponents C_c = -0.5*log2(e)/scale_c^2, scale_c = exp(sigma_c)
    const float C0 = -0.5f * LOG2E * __expf(-2.f * sigma[0]);
    const float C1 = -0.5f * LOG2E * __expf(-2.f * sigma[1]);
    const float C2 = -0.5f * LOG2E * __expf(-2.f * sigma[2]);
    const bool fast = (C0 == C1) && (C0 == C2);

    // Load W (transposed by channel) + bias into shared
    {
        float* W0 = reinterpret_cast<float*>(W0s);
        float* W1 = reinterpret_cast<float*>(W1s);
        float* W2 = reinterpret_cast<float*>(W2s);
        float* Bsc = reinterpret_cast<float*>(Bs4);
        for (int i = tid; i < ZDIM * 3; i += 128) {
            int k = i / 3, c = i - 3 * k;
            float w = W[i];
            if (c == 0) W0[k] = w; else if (c == 1) W1[k] = w; else W2[k] = w;
        }
        for (int i = tid; i < ZDIM; i += 128) Bsc[i] = bfc[i];
    }

    // Precompute per-n (p, q, y0, y1)
    {
        const float*  xb = x + b * NN;
        const float2* yb = reinterpret_cast<const float2*>(y + b * NN * 2);
        #pragma unroll
        for (int i = tid; i < NN; i += 128) {
            float  xv = xb[i];
            float2 yv = yb[i];
            sx[i] = make_float4(C0 * xv * xv, -2.f * C0 * xv, yv.x, yv.y);
        }
    }
    __syncthreads();

    // This warp's 2 m-rows
    const float* tb = t + b * MM + m_base + wrp * 2;
    const float t0 = __ldg(tb + 0);
    const float t1 = __ldg(tb + 1);

    float a00 = 0.f, a01 = 0.f, a02 = 0.f;
    float a10 = 0.f, a11 = 0.f, a12 = 0.f;

    const float4* sp = sx + lane;

    if (fast) {
        // term = exp2(q*t + p); exp2(C0*t^2) factor applied after reduction
        #pragma unroll 4
        for (int i = 0; i < NN / 32; ++i) {
            float4 v = sp[i * 32];                 // coalesced LDS.128
            float e0 = ex2f(fmaf(v.y, t0, v.x));   // 2 independent chains
            float e1 = ex2f(fmaf(v.y, t1, v.x));
            a00 += e0; a01 = fmaf(e0, v.z, a01); a02 = fmaf(e0, v.w, a02);
            a10 += e1; a11 = fmaf(e1, v.z, a11); a12 = fmaf(e1, v.w, a12);
        }
    } else {
        // General per-channel scales: u_m = C0*(t_m - x)^2, e_c = exp2(u * C_c/C0)
        const float f0 = C0 * t0 * t0, f1 = C0 * t1 * t1;
        const float r1 = C1 / C0, r2 = C2 / C0;
        #pragma unroll 4
        for (int i = 0; i < NN / 32; ++i) {
            float4 v = sp[i * 32];
            float u0 = fmaf(v.y, t0, v.x) + f0;
            float u1 = fmaf(v.y, t1, v.x) + f1;
            float e;
            e = ex2f(u0);      a00 += e;
            e = ex2f(u0 * r1); a01 = fmaf(e, v.z, a01);
            e = ex2f(u0 * r2); a02 = fmaf(e, v.w, a02);
            e = ex2f(u1);      a10 += e;
            e = ex2f(u1 * r1); a11 = fmaf(e, v.z, a11);
            e = ex2f(u1 * r2); a12 = fmaf(e, v.w, a12);
        }
    }

    // Warp butterfly reduction of the 6 accumulators
    #pragma unroll
    for (int off = 16; off; off >>= 1) {
        a00 += __shfl_xor_sync(0xffffffffu, a00, off);
        a01 += __shfl_xor_sync(0xffffffffu, a01, off);
        a02 += __shfl_xor_sync(0xffffffffu, a02, off);
        a10 += __shfl_xor_sync(0xffffffffu, a10, off);
        a11 += __shfl_xor_sync(0xffffffffu, a11, off);
        a12 += __shfl_xor_sync(0xffffffffu, a12, off);
    }

    // Lanes 0,1 finalize one m-row each
    if (lane < 2) {
        float s0 = (lane == 0) ? a00 : a10;
        float s1 = (lane == 0) ? a01 : a11;
        float s2 = (lane == 0) ? a02 : a12;
        if (fast) {
            float tm = (lane == 0) ? t0 : t1;
            float E0 = ex2f(C0 * tm * tm);
            s0 *= E0; s1 *= E0; s2 *= E0;
        }
        float inv = 1.f / (s0 + EPSV);
        zfin[wrp * 2 + lane] = make_float4(s0, s1 * inv, s2 * inv, 0.f);
    }
    __syncthreads();

    // Epilogue: out[b, m_base+mi, :] = z @ W^T + bias, float4-coalesced
    float4* out4 = reinterpret_cast<float4*>(out);
    #pragma unroll
    for (int j = tid; j < MT * (ZDIM / 4); j += 128) {
        const int mi = j >> 5;        // ZDIM/4 = 32 float4 per row
        const int k4 = j & 31;
        const float4 z  = zfin[mi];
        const float4 w0 = W0s[k4];
        const float4 w1 = W1s[k4];
        const float4 w2 = W2s[k4];
        const float4 bb = Bs4[k4];
        float4 o;
        o.x = fmaf(z.x, w0.x, fmaf(z.y, w1.x, fmaf(z.z, w2.x, bb.x)));
        o.y = fmaf(z.x, w0.y, fmaf(z.y, w1.y, fmaf(z.z, w2.y, bb.y)));
        o.z = fmaf(z.x, w0.z, fmaf(z.y, w1.z, fmaf(z.z, w2.z, bb.z)));
        o.w = fmaf(z.x, w0.w, fmaf(z.y, w1.w, fmaf(z.z, w2.w, bb.w)));
        out4[(size_t)(b * MM + m_base + mi) * (ZDIM / 4) + k4] = o;
    }
}

extern "C" void kernel_launch(void* const* d_in, const int* in_sizes, int n_in,
                              void* d_out, int out_size)
{
    const float* x     = (const float*)d_in[0];   // (8,1024,1)
    const float* y     = (const float*)d_in[1];   // (8,1024,2)
    const float* t     = (const float*)d_in[2];   // (8,2048,1)
    const float* sigma = (const float*)d_in[3];   // (3,)
    const float* W     = (const float*)d_in[4];   // (128,3)
    const float* bfc   = (const float*)d_in[5];   // (128,)
    float* out = (float*)d_out;                   // (8,2048,128)

    dim3 grid(BB * (MM / MT));   // 2048 blocks
    enc_kernel<<<grid, 128>>>(x, y, t, sigma, W, bfc, out);
}

// round 4
// speedup vs baseline: 1.1604x; 1.1604x over previous
#include <cuda_runtime.h>

// Shapes fixed by dataset: b=8, n=1024, m=2048, x_dim=1, c=3, Z=128
#define BB    8
#define NN    1024
#define MM    2048
#define MT    32      // m-rows per block (4 warps x 8 m each)
#define MREG  8       // m-rows per warp (register-tiled)
#define EPSV  1e-8f
#define LOG2E 1.4426950408889634f

__device__ __forceinline__ float ex2f(float v) {
    float r;
    asm("ex2.approx.ftz.f32 %0, %1;" : "=f"(r) : "f"(v));
    return r;
}

__global__ __launch_bounds__(128)
void enc_kernel(const float* __restrict__ x,
                const float* __restrict__ y,
                const float* __restrict__ t,
                const float* __restrict__ sigma,
                const float* __restrict__ W,
                const float* __restrict__ bfc,
                float* __restrict__ out)
{
    __shared__ float4 sx[NN];     // (p = C0*x^2, q = -2*C0*x, y0, y1)  16KB
    __shared__ float4 zfin[MT];   // (density, zn1, zn2, -)

    const int tid  = threadIdx.x;
    const int lane = tid & 31;
    const int wrp  = tid >> 5;                 // 0..3, each owns 8 m-rows
    const int blk  = blockIdx.x;
    const int b    = blk >> 6;                 // 64 m-tiles per batch
    const int m_base = (blk & 63) * MT;

    // Per-channel exponents C_c = -0.5*log2(e)/scale_c^2, scale_c = exp(sigma_c)
    const float C0 = -0.5f * LOG2E * __expf(-2.f * sigma[0]);
    const float C1 = -0.5f * LOG2E * __expf(-2.f * sigma[1]);
    const float C2 = -0.5f * LOG2E * __expf(-2.f * sigma[2]);
    const bool fast = (C0 == C1) && (C0 == C2);

    // Precompute per-n (p, q, y0, y1) into shared
    {
        const float*  xb = x + b * NN;
        const float2* yb = reinterpret_cast<const float2*>(y + b * NN * 2);
        #pragma unroll
        for (int i = tid; i < NN; i += 128) {
            float  xv = xb[i];
            float2 yv = yb[i];
            sx[i] = make_float4(C0 * xv * xv, -2.f * C0 * xv, yv.x, yv.y);
        }
    }

    // This warp's 8 m-rows (converged loads)
    const float* tb = t + b * MM + m_base + wrp * MREG;
    float tm[MREG];
    #pragma unroll
    for (int j = 0; j < MREG; ++j) tm[j] = __ldg(tb + j);

    __syncthreads();

    float a0[MREG], a1[MREG], a2[MREG];
    #pragma unroll
    for (int j = 0; j < MREG; ++j) { a0[j] = 0.f; a1[j] = 0.f; a2[j] = 0.f; }

    const float4* sp = sx + lane;

    if (fast) {
        // term = exp2(q*t + p); exp2(C0*t^2) factor applied after reduction
        #pragma unroll 4
        for (int i = 0; i < NN / 32; ++i) {
            float4 v = sp[i * 32];                     // coalesced LDS.128, 8-way reuse
            #pragma unroll
            for (int j = 0; j < MREG; ++j) {
                float e = ex2f(fmaf(v.y, tm[j], v.x)); // 8 independent chains
                a0[j] += e;
                a1[j] = fmaf(e, v.z, a1[j]);
                a2[j] = fmaf(e, v.w, a2[j]);
            }
        }
    } else {
        // General per-channel scales: u = C0*(t-x)^2, e_c = exp2(u * C_c/C0)
        float fj[MREG];
        #pragma unroll
        for (int j = 0; j < MREG; ++j) fj[j] = C0 * tm[j] * tm[j];
        const float r1 = C1 / C0, r2 = C2 / C0;
        #pragma unroll 2
        for (int i = 0; i < NN / 32; ++i) {
            float4 v = sp[i * 32];
            #pragma unroll
            for (int j = 0; j < MREG; ++j) {
                float u = fmaf(v.y, tm[j], v.x) + fj[j];
                float e0 = ex2f(u);
                float e1 = ex2f(u * r1);
                float e2 = ex2f(u * r2);
                a0[j] += e0;
                a1[j] = fmaf(e1, v.z, a1[j]);
                a2[j] = fmaf(e2, v.w, a2[j]);
            }
        }
    }

    // Warp butterfly reduction of all 24 accumulators
    #pragma unroll
    for (int off = 16; off; off >>= 1) {
        #pragma unroll
        for (int j = 0; j < MREG; ++j) {
            a0[j] += __shfl_xor_sync(0xffffffffu, a0[j], off);
            a1[j] += __shfl_xor_sync(0xffffffffu, a1[j], off);
            a2[j] += __shfl_xor_sync(0xffffffffu, a2[j], off);
        }
    }

    // Lane j finalizes m-row j (compile-time indices, no spills)
    #pragma unroll
    for (int j = 0; j < MREG; ++j) {
        if (lane == j) {
            float s0 = a0[j], s1 = a1[j], s2 = a2[j];
            if (fast) {
                float E0 = ex2f(C0 * tm[j] * tm[j]);
                s0 *= E0; s1 *= E0; s2 *= E0;
            }
            float inv = 1.f / (s0 + EPSV);
            zfin[wrp * MREG + j] = make_float4(s0, s1 * inv, s2 * inv, 0.f);
        }
    }

    // W + bias into registers (once per thread; column group k4 = lane)
    const int k4 = lane;
    const float4* Wv = reinterpret_cast<const float4*>(W);
    const float4 wa  = __ldg(Wv + 3 * k4);
    const float4 wb  = __ldg(Wv + 3 * k4 + 1);
    const float4 wc  = __ldg(Wv + 3 * k4 + 2);
    const float4 bbv = __ldg(reinterpret_cast<const float4*>(bfc) + k4);

    __syncthreads();

    // Epilogue: out[b, m_base+mi, 4*k4..4*k4+3], coalesced float4 stores
    float4* out4 = reinterpret_cast<float4*>(out);
    const size_t rowbase = (size_t)(b * MM + m_base);
    #pragma unroll
    for (int mi = wrp; mi < MT; mi += 4) {
        float4 z = zfin[mi];     // warp-uniform broadcast LDS
        float4 o;
        o.x = fmaf(z.x, wa.x, fmaf(z.y, wa.y, fmaf(z.z, wa.z, bbv.x)));
        o.y = fmaf(z.x, wa.w, fmaf(z.y, wb.x, fmaf(z.z, wb.y, bbv.y)));
        o.z = fmaf(z.x, wb.z, fmaf(z.y, wb.w, fmaf(z.z, wc.x, bbv.z)));
        o.w = fmaf(z.x, wc.y, fmaf(z.y, wc.z, fmaf(z.z, wc.w, bbv.w)));
        out4[(rowbase + mi) * 32 + k4] = o;
    }
}

extern "C" void kernel_launch(void* const* d_in, const int* in_sizes, int n_in,
                              void* d_out, int out_size)
{
    const float* x     = (const float*)d_in[0];   // (8,1024,1)
    const float* y     = (const float*)d_in[1];   // (8,1024,2)
    const float* t     = (const float*)d_in[2];   // (8,2048,1)
    const float* sigma = (const float*)d_in[3];   // (3,)
    const float* W     = (const float*)d_in[4];   // (128,3)
    const float* bfc   = (const float*)d_in[5];   // (128,)
    float* out = (float*)d_out;                   // (8,2048,128)

    dim3 grid(BB * (MM / MT));   // 512 blocks
    enc_kernel<<<grid, 128>>>(x, y, t, sigma, W, bfc, out);
}